// round 6
// baseline (speedup 1.0000x reference)
#include <cuda_runtime.h>
#include <cuda_fp16.h>
#include <cstdint>

#define MAX_NODES 50048
#define MAX_EDGES 1600000

#define EZ_BLOCKS  768
#define CNT_BLOCKS 256

// Scratch (static __device__ arrays — allocation-free per harness rules)
__device__ __align__(16) float    g_hn[(size_t)MAX_NODES * 128];    // node projections fp32
__device__ __align__(16) __half   g_hnh[(size_t)MAX_NODES * 128];   // node projections fp16
__device__ __align__(16) float    g_sez[(size_t)MAX_NODES * 64];    // sum of ez per dst
__device__ float    g_dinv[MAX_NODES];
__device__ unsigned g_deg[MAX_NODES];
__device__ unsigned g_off[MAX_NODES];
__device__ unsigned g_cur[MAX_NODES];
__device__ unsigned g_total;
__device__ __align__(16) int      g_esrc[MAX_EDGES];                // src ids binned by dst
__device__ __align__(16) float    g_WnT[256 * 128];                 // Wn^T  (k-major)
__device__ __align__(16) float    g_Wr1T[128 * 256];                // Wr[:, :128]^T (k-major)
__device__ __align__(16) float    g_WcT[64 * 256];                  // (Wr2 @ We)^T  (k-major)
__device__ __align__(16) float    g_vbe[256];                       // Wr2 @ be

__device__ __forceinline__ void red_add_v4(float* p, float4 v) {
    asm volatile("red.global.add.v4.f32 [%0], {%1,%2,%3,%4};"
                 :: "l"(p), "f"(v.x), "f"(v.y), "f"(v.z), "f"(v.w) : "memory");
}
__device__ __forceinline__ void red_add_u32(unsigned* p, unsigned v) {
    asm volatile("red.global.add.u32 [%0], %1;" :: "l"(p), "r"(v) : "memory");
}
__device__ __forceinline__ uint64_t dup_f32x2(float a) {
    uint64_t r; asm("mov.b64 %0, {%1, %1};" : "=l"(r) : "f"(a)); return r;
}
__device__ __forceinline__ uint64_t pack_f32x2(float lo, float hi) {
    uint64_t r; asm("mov.b64 %0, {%1, %2};" : "=l"(r) : "f"(lo), "f"(hi)); return r;
}
__device__ __forceinline__ void ffma2(uint64_t& d, uint64_t a, uint64_t b) {
    asm("fma.rn.f32x2 %0, %1, %2, %0;" : "+l"(d) : "l"(a), "l"(b));
}
__device__ __forceinline__ float2 unpack_f32x2(uint64_t v) {
    float2 f; asm("mov.b64 {%0, %1}, %2;" : "=f"(f.x), "=f"(f.y) : "l"(v)); return f;
}

// ---------------------------------------------------------------------------
// K0: init — zero deg/g_total/g_sez, transpose Wn -> WnT, Wr[:, :128] -> Wr1T
// ---------------------------------------------------------------------------
__global__ void init_kernel(const float* __restrict__ Wn, const float* __restrict__ Wr,
                            int n_nodes) {
    int i = blockIdx.x * blockDim.x + threadIdx.x;
    if (i == 0) g_total = 0u;
    if (i < 128 * 256) {                 // Wn [128,256]
        int j = i >> 8, k = i & 255;
        g_WnT[k * 128 + j] = Wn[i];
    }
    if (i < 256 * 128) {                 // Wr1: j<256 rows, k<128 cols
        int j = i >> 7, k = i & 127;
        g_Wr1T[k * 256 + j] = Wr[j * 256 + k];
    }
    if (i < n_nodes) g_deg[i] = 0u;
    if (i < n_nodes * 16)                // g_sez in float4s
        reinterpret_cast<float4*>(g_sez)[i] = make_float4(0.f, 0.f, 0.f, 0.f);
}

// ---------------------------------------------------------------------------
// K1: WcT[k][j] = sum_m Wr[j][128+m] * We[m][k] ;  vbe[j] = Wr2[j]·be
// ---------------------------------------------------------------------------
__global__ __launch_bounds__(64) void wc_kernel(const float* __restrict__ Wr,
                                                const float* __restrict__ We,
                                                const float* __restrict__ be) {
    int j = blockIdx.x;
    int k = threadIdx.x;
    const float* wr2 = Wr + (size_t)j * 256 + 128;
    float acc = 0.f;
#pragma unroll 8
    for (int m = 0; m < 128; m++)
        acc += wr2[m] * We[(size_t)m * 64 + k];
    g_WcT[(size_t)k * 256 + j] = acc;

    __shared__ float red[64];
    red[k] = wr2[k] * be[k] + wr2[k + 64] * be[k + 64];
    __syncthreads();
#pragma unroll
    for (int s = 32; s > 0; s >>= 1) {
        if (k < s) red[k] += red[k + s];
        __syncthreads();
    }
    if (k == 0) g_vbe[j] = red[0];
}

// ---------------------------------------------------------------------------
// K2: fused   (a) ez RED-scatter into g_sez       [blocks 0 .. EZ)
//             (b) in-degree count                  [blocks EZ .. EZ+CNT)
//             (c) hn = x @ Wn^T + bn (FFMA2 GEMM)  [remaining blocks]
//     (a)/(b) are memory/atomic-bound and overlap the compute-bound (c).
// ---------------------------------------------------------------------------
__global__ __launch_bounds__(128) void hn_count_kernel(const float* __restrict__ x,
                                                       const float* __restrict__ bn,
                                                       const float* __restrict__ ez,
                                                       const int* __restrict__ dst,
                                                       int n_nodes, int n_edges) {
    __shared__ __align__(16) float xs[256][34];   // transposed [k][node], even pad
    int tid = threadIdx.x;

    if (blockIdx.x < EZ_BLOCKS) {
        // ---- ez RED scatter: thread per float4 chunk ----
        int nthr = EZ_BLOCKS * 128;
        int total = n_edges * 16;
        for (int idx = blockIdx.x * 128 + tid; idx < total; idx += nthr) {
            int e = idx >> 4, c = idx & 15;
            int d = __ldg(&dst[e]);
            float4 v = reinterpret_cast<const float4*>(ez)[idx];
            red_add_v4(&g_sez[(size_t)d * 64 + 4 * c], v);
        }
        return;
    }
    if (blockIdx.x < EZ_BLOCKS + CNT_BLOCKS) {
        // ---- degree count ----
        int cb = blockIdx.x - EZ_BLOCKS;
        int nthr = CNT_BLOCKS * 128;
        for (int e = cb * 128 + tid; e < n_edges; e += nthr)
            red_add_u32(&g_deg[__ldg(&dst[e])], 1u);
        return;
    }

    int node0 = (blockIdx.x - EZ_BLOCKS - CNT_BLOCKS) * 32;

    // stage x tile transposed
    for (int i = tid; i < 32 * 64; i += 128) {
        int n = i >> 6, c = i & 63;
        float4 v = make_float4(0.f, 0.f, 0.f, 0.f);
        if (node0 + n < n_nodes)
            v = reinterpret_cast<const float4*>(x + (size_t)(node0 + n) * 256)[c];
        xs[4 * c + 0][n] = v.x;
        xs[4 * c + 1][n] = v.y;
        xs[4 * c + 2][n] = v.z;
        xs[4 * c + 3][n] = v.w;
    }
    __syncthreads();

    int jq = tid & 31;   // output quad (128 outputs)
    int ng = tid >> 5;   // 4 groups x 8 nodes (4 pairs)

    float4 bq = *reinterpret_cast<const float4*>(&bn[4 * jq]);
    uint64_t acc[4][4];  // [pair][out]
#pragma unroll
    for (int p = 0; p < 4; p++) {
        acc[p][0] = dup_f32x2(bq.x); acc[p][1] = dup_f32x2(bq.y);
        acc[p][2] = dup_f32x2(bq.z); acc[p][3] = dup_f32x2(bq.w);
    }

#pragma unroll 4
    for (int k = 0; k < 256; k++) {
        float4 w = *reinterpret_cast<const float4*>(&g_WnT[(size_t)k * 128 + 4 * jq]);
        uint64_t wx = dup_f32x2(w.x), wy = dup_f32x2(w.y),
                 wz = dup_f32x2(w.z), ww = dup_f32x2(w.w);
#pragma unroll
        for (int p = 0; p < 4; p++) {
            uint64_t t2 = *reinterpret_cast<const uint64_t*>(&xs[k][ng * 8 + 2 * p]);
            ffma2(acc[p][0], wx, t2);
            ffma2(acc[p][1], wy, t2);
            ffma2(acc[p][2], wz, t2);
            ffma2(acc[p][3], ww, t2);
        }
    }

#pragma unroll
    for (int p = 0; p < 4; p++) {
        float2 o0 = unpack_f32x2(acc[p][0]);
        float2 o1 = unpack_f32x2(acc[p][1]);
        float2 o2 = unpack_f32x2(acc[p][2]);
        float2 o3 = unpack_f32x2(acc[p][3]);
        int n = node0 + ng * 8 + 2 * p;
        if (n < n_nodes) {
            float4 f = make_float4(o0.x, o1.x, o2.x, o3.x);
            *reinterpret_cast<float4*>(&g_hn[(size_t)n * 128 + 4 * jq]) = f;
            uint2 u;
            *reinterpret_cast<__half2*>(&u.x) = __floats2half2_rn(f.x, f.y);
            *reinterpret_cast<__half2*>(&u.y) = __floats2half2_rn(f.z, f.w);
            reinterpret_cast<uint2*>(g_hnh)[(size_t)n * 32 + jq] = u;
        }
        if (n + 1 < n_nodes) {
            float4 f = make_float4(o0.y, o1.y, o2.y, o3.y);
            *reinterpret_cast<float4*>(&g_hn[(size_t)(n + 1) * 128 + 4 * jq]) = f;
            uint2 u;
            *reinterpret_cast<__half2*>(&u.x) = __floats2half2_rn(f.x, f.y);
            *reinterpret_cast<__half2*>(&u.y) = __floats2half2_rn(f.z, f.w);
            reinterpret_cast<uint2*>(g_hnh)[(size_t)(n + 1) * 32 + jq] = u;
        }
    }
}

// ---------------------------------------------------------------------------
// K3: parallel offset allocator — warp-scan + one atomicAdd per warp.
// ---------------------------------------------------------------------------
__global__ __launch_bounds__(256) void alloc_kernel(int n_nodes) {
    int i = blockIdx.x * blockDim.x + threadIdx.x;
    int lane = threadIdx.x & 31;
    unsigned d = (i < n_nodes) ? g_deg[i] : 0u;

    unsigned s = d;
#pragma unroll
    for (int o = 1; o < 32; o <<= 1) {
        unsigned v = __shfl_up_sync(0xffffffffu, s, o);
        if (lane >= o) s += v;
    }
    unsigned warptot = __shfl_sync(0xffffffffu, s, 31);
    unsigned base = 0;
    if (lane == 31 && warptot > 0) base = atomicAdd(&g_total, warptot);
    base = __shfl_sync(0xffffffffu, base, 31);

    if (i < n_nodes) {
        unsigned off = base + s - d;
        g_off[i] = off;
        g_cur[i] = off;
    }
}

// ---------------------------------------------------------------------------
// K4: bin edge srcs by dst
// ---------------------------------------------------------------------------
__global__ void fill_kernel(const int* __restrict__ src, const int* __restrict__ dst,
                            int n_edges) {
    int stride = gridDim.x * blockDim.x;
    for (int e = blockIdx.x * blockDim.x + threadIdx.x; e < n_edges; e += stride) {
        int d = __ldg(&dst[e]);
        unsigned pos = atomicAdd(&g_cur[d], 1u);
        g_esrc[pos] = __ldg(&src[e]);
    }
}

// ---------------------------------------------------------------------------
// K5: fused gather + reduce GEMM.
//     Phase 1: 4 warps gather fp16 hn[src] sums for 8 nodes each, build
//              transposed state tile in smem.
//     Phase 2: out = Wr1@s1 + Wc@s2 + dinv*vbe + br (FFMA2), zero if deg==0.
// ---------------------------------------------------------------------------
__global__ __launch_bounds__(128) void node_kernel(const float* __restrict__ br,
                                                   float* __restrict__ out,
                                                   int n_nodes) {
    __shared__ __align__(16) float ts[192][34];   // transposed [k][node]
    __shared__ float dinv_s[32];
    __shared__ unsigned deg_s[32];
    int node0 = blockIdx.x * 32;
    int tid = threadIdx.x;
    int lane = tid & 31;
    int wrp = tid >> 5;

    const uint2* hb = reinterpret_cast<const uint2*>(g_hnh);

    // ---- phase 1: gather ----
#pragma unroll 1
    for (int r = 0; r < 8; r++) {
        int nl = wrp * 8 + r;
        int n = node0 + nl;
        if (n < n_nodes) {
            unsigned off = g_off[n];
            int deg = (int)g_deg[n];
            const int* sp = g_esrc + off;

            float4 ah = make_float4(0.f, 0.f, 0.f, 0.f);
            int i = 0;
            int d4 = deg & ~3;
            for (; i < d4; i += 4) {
                int s0 = __ldg(&sp[i + 0]);
                int s1 = __ldg(&sp[i + 1]);
                int s2 = __ldg(&sp[i + 2]);
                int s3 = __ldg(&sp[i + 3]);
                uint2 u0 = __ldg(&hb[(size_t)s0 * 32 + lane]);
                uint2 u1 = __ldg(&hb[(size_t)s1 * 32 + lane]);
                uint2 u2 = __ldg(&hb[(size_t)s2 * 32 + lane]);
                uint2 u3 = __ldg(&hb[(size_t)s3 * 32 + lane]);
                float2 a0 = __half22float2(*reinterpret_cast<__half2*>(&u0.x));
                float2 b0 = __half22float2(*reinterpret_cast<__half2*>(&u0.y));
                float2 a1 = __half22float2(*reinterpret_cast<__half2*>(&u1.x));
                float2 b1 = __half22float2(*reinterpret_cast<__half2*>(&u1.y));
                float2 a2 = __half22float2(*reinterpret_cast<__half2*>(&u2.x));
                float2 b2 = __half22float2(*reinterpret_cast<__half2*>(&u2.y));
                float2 a3 = __half22float2(*reinterpret_cast<__half2*>(&u3.x));
                float2 b3 = __half22float2(*reinterpret_cast<__half2*>(&u3.y));
                ah.x += a0.x + a1.x + a2.x + a3.x;
                ah.y += a0.y + a1.y + a2.y + a3.y;
                ah.z += b0.x + b1.x + b2.x + b3.x;
                ah.w += b0.y + b1.y + b2.y + b3.y;
            }
            for (; i < deg; i++) {
                int s0 = __ldg(&sp[i]);
                uint2 u0 = __ldg(&hb[(size_t)s0 * 32 + lane]);
                float2 a0 = __half22float2(*reinterpret_cast<__half2*>(&u0.x));
                float2 b0 = __half22float2(*reinterpret_cast<__half2*>(&u0.y));
                ah.x += a0.x; ah.y += a0.y; ah.z += b0.x; ah.w += b0.y;
            }

            float inv = 1.0f / (float)(deg + 1);
            float4 self = *reinterpret_cast<const float4*>(&g_hn[(size_t)n * 128 + 4 * lane]);
            ts[4 * lane + 0][nl] = (self.x + ah.x) * inv;
            ts[4 * lane + 1][nl] = (self.y + ah.y) * inv;
            ts[4 * lane + 2][nl] = (self.z + ah.z) * inv;
            ts[4 * lane + 3][nl] = (self.w + ah.w) * inv;
            float2 sz = *reinterpret_cast<const float2*>(&g_sez[(size_t)n * 64 + 2 * lane]);
            ts[128 + 2 * lane + 0][nl] = sz.x * inv;
            ts[128 + 2 * lane + 1][nl] = sz.y * inv;
            if (lane == 0) {
                deg_s[nl] = (unsigned)deg;
                dinv_s[nl] = (float)deg * inv;
            }
        } else {
            ts[4 * lane + 0][nl] = 0.f;
            ts[4 * lane + 1][nl] = 0.f;
            ts[4 * lane + 2][nl] = 0.f;
            ts[4 * lane + 3][nl] = 0.f;
            ts[128 + 2 * lane + 0][nl] = 0.f;
            ts[128 + 2 * lane + 1][nl] = 0.f;
            if (lane == 0) { deg_s[nl] = 0u; dinv_s[nl] = 0.f; }
        }
    }
    __syncthreads();

    // ---- phase 2: reduce GEMM ----
    int jq = tid & 63;   // output quad (256 outputs)
    int ng = tid >> 6;   // 2 groups x 16 nodes (8 pairs)

    float4 brv = *reinterpret_cast<const float4*>(&br[4 * jq]);
    float4 vb  = *reinterpret_cast<const float4*>(&g_vbe[4 * jq]);

    uint64_t acc[8][4];  // [pair][out]
#pragma unroll
    for (int p = 0; p < 8; p++) {
        float d0 = dinv_s[ng * 16 + 2 * p];
        float d1 = dinv_s[ng * 16 + 2 * p + 1];
        acc[p][0] = pack_f32x2(brv.x + d0 * vb.x, brv.x + d1 * vb.x);
        acc[p][1] = pack_f32x2(brv.y + d0 * vb.y, brv.y + d1 * vb.y);
        acc[p][2] = pack_f32x2(brv.z + d0 * vb.z, brv.z + d1 * vb.z);
        acc[p][3] = pack_f32x2(brv.w + d0 * vb.w, brv.w + d1 * vb.w);
    }

#pragma unroll 2
    for (int k = 0; k < 128; k++) {
        float4 w = *reinterpret_cast<const float4*>(&g_Wr1T[(size_t)k * 256 + 4 * jq]);
        uint64_t wx = dup_f32x2(w.x), wy = dup_f32x2(w.y),
                 wz = dup_f32x2(w.z), ww = dup_f32x2(w.w);
#pragma unroll
        for (int p = 0; p < 8; p++) {
            uint64_t t2 = *reinterpret_cast<const uint64_t*>(&ts[k][ng * 16 + 2 * p]);
            ffma2(acc[p][0], wx, t2);
            ffma2(acc[p][1], wy, t2);
            ffma2(acc[p][2], wz, t2);
            ffma2(acc[p][3], ww, t2);
        }
    }
#pragma unroll 2
    for (int k = 0; k < 64; k++) {
        float4 w = *reinterpret_cast<const float4*>(&g_WcT[(size_t)k * 256 + 4 * jq]);
        uint64_t wx = dup_f32x2(w.x), wy = dup_f32x2(w.y),
                 wz = dup_f32x2(w.z), ww = dup_f32x2(w.w);
#pragma unroll
        for (int p = 0; p < 8; p++) {
            uint64_t t2 = *reinterpret_cast<const uint64_t*>(&ts[128 + k][ng * 16 + 2 * p]);
            ffma2(acc[p][0], wx, t2);
            ffma2(acc[p][1], wy, t2);
            ffma2(acc[p][2], wz, t2);
            ffma2(acc[p][3], ww, t2);
        }
    }

#pragma unroll
    for (int p = 0; p < 8; p++) {
        float2 o0 = unpack_f32x2(acc[p][0]);
        float2 o1 = unpack_f32x2(acc[p][1]);
        float2 o2 = unpack_f32x2(acc[p][2]);
        float2 o3 = unpack_f32x2(acc[p][3]);
        int n = node0 + ng * 16 + 2 * p;
        if (n < n_nodes) {
            float4 o = make_float4(o0.x, o1.x, o2.x, o3.x);
            if (deg_s[ng * 16 + 2 * p] == 0u) o = make_float4(0.f, 0.f, 0.f, 0.f);
            *reinterpret_cast<float4*>(&out[(size_t)n * 256 + 4 * jq]) = o;
        }
        if (n + 1 < n_nodes) {
            float4 o = make_float4(o0.y, o1.y, o2.y, o3.y);
            if (deg_s[ng * 16 + 2 * p + 1] == 0u) o = make_float4(0.f, 0.f, 0.f, 0.f);
            *reinterpret_cast<float4*>(&out[(size_t)(n + 1) * 256 + 4 * jq]) = o;
        }
    }
}

// ---------------------------------------------------------------------------
extern "C" void kernel_launch(void* const* d_in, const int* in_sizes, int n_in,
                              void* d_out, int out_size) {
    const float* x  = (const float*)d_in[0];
    const float* ez = (const float*)d_in[1];
    const int* src  = (const int*)d_in[2];
    const int* dst  = (const int*)d_in[3];
    const float* Wn = (const float*)d_in[4];
    const float* bn = (const float*)d_in[5];
    const float* We = (const float*)d_in[6];
    const float* be = (const float*)d_in[7];
    const float* Wr = (const float*)d_in[8];
    const float* br = (const float*)d_in[9];
    float* out = (float*)d_out;

    int n_nodes = in_sizes[0] / 256;
    int n_edges = in_sizes[2];

    int init_elems = n_nodes * 16;               // sez float4s dominate
    if (init_elems < 128 * 256) init_elems = 128 * 256;
    init_kernel<<<(init_elems + 255) / 256, 256>>>(Wn, Wr, n_nodes);
    wc_kernel<<<256, 64>>>(Wr, We, be);

    int hn_blocks = (n_nodes + 31) / 32;
    hn_count_kernel<<<EZ_BLOCKS + CNT_BLOCKS + hn_blocks, 128>>>(
        x, bn, ez, dst, n_nodes, n_edges);

    alloc_kernel<<<(n_nodes + 255) / 256, 256>>>(n_nodes);
    fill_kernel<<<1024, 256>>>(src, dst, n_edges);
    node_kernel<<<(n_nodes + 31) / 32, 128>>>(br, out, n_nodes);
}

// round 7
// speedup vs baseline: 1.1534x; 1.1534x over previous
#include <cuda_runtime.h>
#include <cuda_fp16.h>
#include <cstdint>

#define MAX_NODES 50048
#define MAX_EDGES 1600000

// Scratch (static __device__ arrays — allocation-free per harness rules)
__device__ __align__(16) float    g_hn[(size_t)MAX_NODES * 128];    // node projections fp32
__device__ __align__(16) __half   g_hnh[(size_t)MAX_NODES * 128];   // fp16 mirror for gather
__device__ __align__(16) float    g_state[(size_t)MAX_NODES * 192]; // mean state (scaled)
__device__ float    g_dinv[MAX_NODES];
__device__ unsigned g_deg[MAX_NODES];
__device__ unsigned g_off[MAX_NODES];
__device__ unsigned g_cur[MAX_NODES];
__device__ unsigned g_total;
__device__ __align__(16) int2     g_epair[MAX_EDGES];               // (src, edge_id) by dst
__device__ __align__(16) float    g_WnT[256 * 128];                 // Wn^T  (k-major)
__device__ __align__(16) float    g_Wr1T[128 * 256];                // Wr[:, :128]^T (k-major)
__device__ __align__(16) float    g_WcT[64 * 256];                  // (Wr2 @ We)^T  (k-major)
__device__ __align__(16) float    g_vbe[256];                       // Wr2 @ be

__device__ __forceinline__ void red_add_u32(unsigned* p, unsigned v) {
    asm volatile("red.global.add.u32 [%0], %1;" :: "l"(p), "r"(v) : "memory");
}
__device__ __forceinline__ uint64_t dup_f32x2(float a) {
    uint64_t r; asm("mov.b64 %0, {%1, %1};" : "=l"(r) : "f"(a)); return r;
}
__device__ __forceinline__ uint64_t pack_f32x2(float lo, float hi) {
    uint64_t r; asm("mov.b64 %0, {%1, %2};" : "=l"(r) : "f"(lo), "f"(hi)); return r;
}
__device__ __forceinline__ void ffma2(uint64_t& d, uint64_t a, uint64_t b) {
    asm("fma.rn.f32x2 %0, %1, %2, %0;" : "+l"(d) : "l"(a), "l"(b));
}
__device__ __forceinline__ float2 unpack_f32x2(uint64_t v) {
    float2 f; asm("mov.b64 {%0, %1}, %2;" : "=f"(f.x), "=f"(f.y) : "l"(v)); return f;
}

// ---------------------------------------------------------------------------
// K0: init — zero deg/g_total, transpose Wn -> WnT and Wr[:, :128] -> Wr1T
// ---------------------------------------------------------------------------
__global__ void init_kernel(const float* __restrict__ Wn, const float* __restrict__ Wr,
                            int n_nodes) {
    int i = blockIdx.x * blockDim.x + threadIdx.x;
    if (i == 0) g_total = 0u;
    if (i < 128 * 256) {                 // Wn [128,256]
        int j = i >> 8, k = i & 255;
        g_WnT[k * 128 + j] = Wn[i];
    }
    if (i < 256 * 128) {                 // Wr1: j<256 rows, k<128 cols
        int j = i >> 7, k = i & 127;
        g_Wr1T[k * 256 + j] = Wr[j * 256 + k];
    }
    if (i < n_nodes) g_deg[i] = 0u;
}

// ---------------------------------------------------------------------------
// K1: WcT[k][j] = sum_m Wr[j][128+m] * We[m][k] ;  vbe[j] = Wr2[j]·be
// ---------------------------------------------------------------------------
__global__ __launch_bounds__(64) void wc_kernel(const float* __restrict__ Wr,
                                                const float* __restrict__ We,
                                                const float* __restrict__ be) {
    int j = blockIdx.x;
    int k = threadIdx.x;
    const float* wr2 = Wr + (size_t)j * 256 + 128;
    float acc = 0.f;
#pragma unroll 8
    for (int m = 0; m < 128; m++)
        acc += wr2[m] * We[(size_t)m * 64 + k];
    g_WcT[(size_t)k * 256 + j] = acc;

    __shared__ float red[64];
    red[k] = wr2[k] * be[k] + wr2[k + 64] * be[k + 64];
    __syncthreads();
#pragma unroll
    for (int s = 32; s > 0; s >>= 1) {
        if (k < s) red[k] += red[k + s];
        __syncthreads();
    }
    if (k == 0) g_vbe[j] = red[0];
}

// ---------------------------------------------------------------------------
// K2: fused   (a) hn = x @ Wn^T + bn  (f32x2 packed, 32 nodes x 128 outs/CTA)
//                 + fp16 mirror write
//             (b) count in-degree (extra blocks)
// ---------------------------------------------------------------------------
__global__ __launch_bounds__(128) void hn_count_kernel(const float* __restrict__ x,
                                                       const float* __restrict__ bn,
                                                       const int* __restrict__ dst,
                                                       int n_nodes, int n_edges,
                                                       int hn_blocks) {
    __shared__ __align__(16) float xs[256][34];   // transposed [k][node], even pad
    int tid = threadIdx.x;

    if (blockIdx.x >= hn_blocks) {
        // ---- count part ----
        int cb = blockIdx.x - hn_blocks;
        int nthr = (gridDim.x - hn_blocks) * 128;
        for (int e = cb * 128 + tid; e < n_edges; e += nthr)
            red_add_u32(&g_deg[__ldg(&dst[e])], 1u);
        return;
    }

    int node0 = blockIdx.x * 32;

    // stage x tile transposed
    for (int i = tid; i < 32 * 64; i += 128) {
        int n = i >> 6, c = i & 63;
        float4 v = make_float4(0.f, 0.f, 0.f, 0.f);
        if (node0 + n < n_nodes)
            v = reinterpret_cast<const float4*>(x + (size_t)(node0 + n) * 256)[c];
        xs[4 * c + 0][n] = v.x;
        xs[4 * c + 1][n] = v.y;
        xs[4 * c + 2][n] = v.z;
        xs[4 * c + 3][n] = v.w;
    }
    __syncthreads();

    int jq = tid & 31;   // output quad (128 outputs)
    int ng = tid >> 5;   // 4 groups x 8 nodes (4 pairs)

    float4 bq = *reinterpret_cast<const float4*>(&bn[4 * jq]);
    uint64_t acc[4][4];  // [pair][out]
#pragma unroll
    for (int p = 0; p < 4; p++) {
        acc[p][0] = dup_f32x2(bq.x); acc[p][1] = dup_f32x2(bq.y);
        acc[p][2] = dup_f32x2(bq.z); acc[p][3] = dup_f32x2(bq.w);
    }

#pragma unroll 4
    for (int k = 0; k < 256; k++) {
        float4 w = *reinterpret_cast<const float4*>(&g_WnT[(size_t)k * 128 + 4 * jq]);
        uint64_t wx = dup_f32x2(w.x), wy = dup_f32x2(w.y),
                 wz = dup_f32x2(w.z), ww = dup_f32x2(w.w);
#pragma unroll
        for (int p = 0; p < 4; p++) {
            uint64_t t2 = *reinterpret_cast<const uint64_t*>(&xs[k][ng * 8 + 2 * p]);
            ffma2(acc[p][0], wx, t2);
            ffma2(acc[p][1], wy, t2);
            ffma2(acc[p][2], wz, t2);
            ffma2(acc[p][3], ww, t2);
        }
    }

#pragma unroll
    for (int p = 0; p < 4; p++) {
        float2 o0 = unpack_f32x2(acc[p][0]);
        float2 o1 = unpack_f32x2(acc[p][1]);
        float2 o2 = unpack_f32x2(acc[p][2]);
        float2 o3 = unpack_f32x2(acc[p][3]);
        int n = node0 + ng * 8 + 2 * p;
        if (n < n_nodes) {
            float4 f = make_float4(o0.x, o1.x, o2.x, o3.x);
            *reinterpret_cast<float4*>(&g_hn[(size_t)n * 128 + 4 * jq]) = f;
            uint2 u;
            *reinterpret_cast<__half2*>(&u.x) = __floats2half2_rn(f.x, f.y);
            *reinterpret_cast<__half2*>(&u.y) = __floats2half2_rn(f.z, f.w);
            reinterpret_cast<uint2*>(g_hnh)[(size_t)n * 32 + jq] = u;
        }
        if (n + 1 < n_nodes) {
            float4 f = make_float4(o0.y, o1.y, o2.y, o3.y);
            *reinterpret_cast<float4*>(&g_hn[(size_t)(n + 1) * 128 + 4 * jq]) = f;
            uint2 u;
            *reinterpret_cast<__half2*>(&u.x) = __floats2half2_rn(f.x, f.y);
            *reinterpret_cast<__half2*>(&u.y) = __floats2half2_rn(f.z, f.w);
            reinterpret_cast<uint2*>(g_hnh)[(size_t)(n + 1) * 32 + jq] = u;
        }
    }
}

// ---------------------------------------------------------------------------
// K3: parallel offset allocator — warp-scan + one atomicAdd per warp.
// ---------------------------------------------------------------------------
__global__ __launch_bounds__(256) void alloc_kernel(int n_nodes) {
    int i = blockIdx.x * blockDim.x + threadIdx.x;
    int lane = threadIdx.x & 31;
    unsigned d = (i < n_nodes) ? g_deg[i] : 0u;

    unsigned s = d;
#pragma unroll
    for (int o = 1; o < 32; o <<= 1) {
        unsigned v = __shfl_up_sync(0xffffffffu, s, o);
        if (lane >= o) s += v;
    }
    unsigned warptot = __shfl_sync(0xffffffffu, s, 31);
    unsigned base = 0;
    if (lane == 31 && warptot > 0) base = atomicAdd(&g_total, warptot);
    base = __shfl_sync(0xffffffffu, base, 31);

    if (i < n_nodes) {
        unsigned off = base + s - d;
        g_off[i] = off;
        g_cur[i] = off;
    }
}

// ---------------------------------------------------------------------------
// K4: bin edges by dst:  g_epair[pos] = (src, e)
// ---------------------------------------------------------------------------
__global__ void fill_kernel(const int* __restrict__ src, const int* __restrict__ dst,
                            int n_edges) {
    int stride = gridDim.x * blockDim.x;
    for (int e = blockIdx.x * blockDim.x + threadIdx.x; e < n_edges; e += stride) {
        int d = __ldg(&dst[e]);
        unsigned pos = atomicAdd(&g_cur[d], 1u);
        g_epair[pos] = make_int2(__ldg(&src[e]), e);
    }
}

// ---------------------------------------------------------------------------
// K5: warp-per-node gather (fp16 hn mirror for neighbors; fp32 self/accum),
//     write scaled mean-state (192 floats/node).
// ---------------------------------------------------------------------------
__global__ __launch_bounds__(256) void gather_kernel(const float* __restrict__ ez,
                                                     int n_nodes) {
    int lane = threadIdx.x & 31;
    int n = blockIdx.x * 8 + (threadIdx.x >> 5);
    if (n >= n_nodes) return;

    unsigned off = g_off[n];
    int deg = (int)g_deg[n];
    const int2* ep = g_epair + off;
    const uint2* hb = reinterpret_cast<const uint2*>(g_hnh);

    float4 ah = make_float4(0.f, 0.f, 0.f, 0.f);
    float2 ae = make_float2(0.f, 0.f);

    int i = 0;
    int d4 = deg & ~3;
    for (; i < d4; i += 4) {
        int2 p0 = __ldg(&ep[i + 0]);
        int2 p1 = __ldg(&ep[i + 1]);
        int2 p2 = __ldg(&ep[i + 2]);
        int2 p3 = __ldg(&ep[i + 3]);
        uint2 u0 = __ldg(&hb[(size_t)p0.x * 32 + lane]);
        uint2 u1 = __ldg(&hb[(size_t)p1.x * 32 + lane]);
        uint2 u2 = __ldg(&hb[(size_t)p2.x * 32 + lane]);
        uint2 u3 = __ldg(&hb[(size_t)p3.x * 32 + lane]);
        float2 e0 = *reinterpret_cast<const float2*>(&ez[(size_t)p0.y * 64 + 2 * lane]);
        float2 e1 = *reinterpret_cast<const float2*>(&ez[(size_t)p1.y * 64 + 2 * lane]);
        float2 e2 = *reinterpret_cast<const float2*>(&ez[(size_t)p2.y * 64 + 2 * lane]);
        float2 e3 = *reinterpret_cast<const float2*>(&ez[(size_t)p3.y * 64 + 2 * lane]);
        float2 a0 = __half22float2(*reinterpret_cast<__half2*>(&u0.x));
        float2 b0 = __half22float2(*reinterpret_cast<__half2*>(&u0.y));
        float2 a1 = __half22float2(*reinterpret_cast<__half2*>(&u1.x));
        float2 b1 = __half22float2(*reinterpret_cast<__half2*>(&u1.y));
        float2 a2 = __half22float2(*reinterpret_cast<__half2*>(&u2.x));
        float2 b2 = __half22float2(*reinterpret_cast<__half2*>(&u2.y));
        float2 a3 = __half22float2(*reinterpret_cast<__half2*>(&u3.x));
        float2 b3 = __half22float2(*reinterpret_cast<__half2*>(&u3.y));
        ah.x += a0.x + a1.x + a2.x + a3.x;
        ah.y += a0.y + a1.y + a2.y + a3.y;
        ah.z += b0.x + b1.x + b2.x + b3.x;
        ah.w += b0.y + b1.y + b2.y + b3.y;
        ae.x += e0.x + e1.x + e2.x + e3.x;
        ae.y += e0.y + e1.y + e2.y + e3.y;
    }
    for (; i < deg; i++) {
        int2 p = __ldg(&ep[i]);
        uint2 u0 = __ldg(&hb[(size_t)p.x * 32 + lane]);
        float2 ev = *reinterpret_cast<const float2*>(&ez[(size_t)p.y * 64 + 2 * lane]);
        float2 a0 = __half22float2(*reinterpret_cast<__half2*>(&u0.x));
        float2 b0 = __half22float2(*reinterpret_cast<__half2*>(&u0.y));
        ah.x += a0.x; ah.y += a0.y; ah.z += b0.x; ah.w += b0.y;
        ae.x += ev.x; ae.y += ev.y;
    }

    float inv = 1.0f / (float)(deg + 1);
    float4 selfh = *reinterpret_cast<const float4*>(&g_hn[(size_t)n * 128 + 4 * lane]);

    float* st = &g_state[(size_t)n * 192];
    *reinterpret_cast<float4*>(&st[4 * lane]) =
        make_float4((selfh.x + ah.x) * inv, (selfh.y + ah.y) * inv,
                    (selfh.z + ah.z) * inv, (selfh.w + ah.w) * inv);
    *reinterpret_cast<float2*>(&st[128 + 2 * lane]) = make_float2(ae.x * inv, ae.y * inv);
    if (lane == 0) g_dinv[n] = (float)deg * inv;
}

// ---------------------------------------------------------------------------
// K6: out = Wr1@s1 + Wc@s2 + dinv*vbe + br ; zero if deg==0
//     (f32x2 packed, 32 nodes x 256 outs per CTA, 128 threads)
// ---------------------------------------------------------------------------
__global__ __launch_bounds__(128) void node_kernel(const float* __restrict__ br,
                                                   float* __restrict__ out,
                                                   int n_nodes) {
    __shared__ __align__(16) float ts[192][34];   // transposed [k][node]
    __shared__ float dinv_s[32];
    __shared__ unsigned deg_s[32];
    int node0 = blockIdx.x * 32;
    int tid = threadIdx.x;

    if (tid < 32) {
        int n = node0 + tid;
        deg_s[tid] = (n < n_nodes) ? g_deg[n] : 0u;
        dinv_s[tid] = (n < n_nodes) ? g_dinv[n] : 0.f;
    }

    for (int i = tid; i < 32 * 48; i += 128) {
        int n = i / 48, c = i % 48;
        int gn = node0 + n;
        float4 v = make_float4(0.f, 0.f, 0.f, 0.f);
        if (gn < n_nodes)
            v = reinterpret_cast<const float4*>(&g_state[(size_t)gn * 192])[c];
        ts[4 * c + 0][n] = v.x;
        ts[4 * c + 1][n] = v.y;
        ts[4 * c + 2][n] = v.z;
        ts[4 * c + 3][n] = v.w;
    }
    __syncthreads();

    int jq = tid & 63;   // output quad (256 outputs)
    int ng = tid >> 6;   // 2 groups x 16 nodes (8 pairs)

    float4 brv = *reinterpret_cast<const float4*>(&br[4 * jq]);
    float4 vb  = *reinterpret_cast<const float4*>(&g_vbe[4 * jq]);

    uint64_t acc[8][4];  // [pair][out]
#pragma unroll
    for (int p = 0; p < 8; p++) {
        float d0 = dinv_s[ng * 16 + 2 * p];
        float d1 = dinv_s[ng * 16 + 2 * p + 1];
        acc[p][0] = pack_f32x2(brv.x + d0 * vb.x, brv.x + d1 * vb.x);
        acc[p][1] = pack_f32x2(brv.y + d0 * vb.y, brv.y + d1 * vb.y);
        acc[p][2] = pack_f32x2(brv.z + d0 * vb.z, brv.z + d1 * vb.z);
        acc[p][3] = pack_f32x2(brv.w + d0 * vb.w, brv.w + d1 * vb.w);
    }

#pragma unroll 2
    for (int k = 0; k < 128; k++) {
        float4 w = *reinterpret_cast<const float4*>(&g_Wr1T[(size_t)k * 256 + 4 * jq]);
        uint64_t wx = dup_f32x2(w.x), wy = dup_f32x2(w.y),
                 wz = dup_f32x2(w.z), ww = dup_f32x2(w.w);
#pragma unroll
        for (int p = 0; p < 8; p++) {
            uint64_t t2 = *reinterpret_cast<const uint64_t*>(&ts[k][ng * 16 + 2 * p]);
            ffma2(acc[p][0], wx, t2);
            ffma2(acc[p][1], wy, t2);
            ffma2(acc[p][2], wz, t2);
            ffma2(acc[p][3], ww, t2);
        }
    }
#pragma unroll 2
    for (int k = 0; k < 64; k++) {
        float4 w = *reinterpret_cast<const float4*>(&g_WcT[(size_t)k * 256 + 4 * jq]);
        uint64_t wx = dup_f32x2(w.x), wy = dup_f32x2(w.y),
                 wz = dup_f32x2(w.z), ww = dup_f32x2(w.w);
#pragma unroll
        for (int p = 0; p < 8; p++) {
            uint64_t t2 = *reinterpret_cast<const uint64_t*>(&ts[128 + k][ng * 16 + 2 * p]);
            ffma2(acc[p][0], wx, t2);
            ffma2(acc[p][1], wy, t2);
            ffma2(acc[p][2], wz, t2);
            ffma2(acc[p][3], ww, t2);
        }
    }

#pragma unroll
    for (int p = 0; p < 8; p++) {
        float2 o0 = unpack_f32x2(acc[p][0]);
        float2 o1 = unpack_f32x2(acc[p][1]);
        float2 o2 = unpack_f32x2(acc[p][2]);
        float2 o3 = unpack_f32x2(acc[p][3]);
        int n = node0 + ng * 16 + 2 * p;
        if (n < n_nodes) {
            float4 o = make_float4(o0.x, o1.x, o2.x, o3.x);
            if (deg_s[ng * 16 + 2 * p] == 0u) o = make_float4(0.f, 0.f, 0.f, 0.f);
            *reinterpret_cast<float4*>(&out[(size_t)n * 256 + 4 * jq]) = o;
        }
        if (n + 1 < n_nodes) {
            float4 o = make_float4(o0.y, o1.y, o2.y, o3.y);
            if (deg_s[ng * 16 + 2 * p + 1] == 0u) o = make_float4(0.f, 0.f, 0.f, 0.f);
            *reinterpret_cast<float4*>(&out[(size_t)(n + 1) * 256 + 4 * jq]) = o;
        }
    }
}

// ---------------------------------------------------------------------------
extern "C" void kernel_launch(void* const* d_in, const int* in_sizes, int n_in,
                              void* d_out, int out_size) {
    const float* x  = (const float*)d_in[0];
    const float* ez = (const float*)d_in[1];
    const int* src  = (const int*)d_in[2];
    const int* dst  = (const int*)d_in[3];
    const float* Wn = (const float*)d_in[4];
    const float* bn = (const float*)d_in[5];
    const float* We = (const float*)d_in[6];
    const float* be = (const float*)d_in[7];
    const float* Wr = (const float*)d_in[8];
    const float* br = (const float*)d_in[9];
    float* out = (float*)d_out;

    int n_nodes = in_sizes[0] / 256;
    int n_edges = in_sizes[2];

    int init_elems = (n_nodes > 128 * 256) ? n_nodes : 128 * 256;
    init_kernel<<<(init_elems + 255) / 256, 256>>>(Wn, Wr, n_nodes);
    wc_kernel<<<256, 64>>>(Wr, We, be);

    int hn_blocks = (n_nodes + 31) / 32;
    hn_count_kernel<<<hn_blocks + 256, 128>>>(x, bn, dst, n_nodes, n_edges, hn_blocks);

    alloc_kernel<<<(n_nodes + 255) / 256, 256>>>(n_nodes);
    fill_kernel<<<1024, 256>>>(src, dst, n_edges);
    gather_kernel<<<(n_nodes + 7) / 8, 256>>>(ez, n_nodes);
    node_kernel<<<(n_nodes + 31) / 32, 128>>>(br, out, n_nodes);
}